// round 1
// baseline (speedup 1.0000x reference)
#include <cuda_runtime.h>
#include <cstdint>

#define NAG   8
#define BATCH 32768
#define SDIM  128
#define ADIM  16
#define HID   128
#define HEADS 4
#define AD    32

// ---------------- scratch (device globals; no allocation allowed) ----------------
__device__ float g_sa   [(size_t)NAG * BATCH * HID];   // sa_enc
__device__ float g_se   [(size_t)NAG * BATCH * HID];   // s_enc
__device__ float g_Kb   [(size_t)NAG * BATCH * HID];   // K, layout [n][b][k*32+d]
__device__ float g_Qb   [(size_t)NAG * BATCH * HID];   // Q
__device__ float g_Vb   [(size_t)NAG * BATCH * HID];   // V
__device__ float g_oth  [(size_t)NAG * BATCH * HID];   // attention output ("other")

// ---------------- generic per-agent SGEMM: C[n] = act(A[n] @ W[n] + b[n]) --------
// A = concat(A1 (a1w cols), A2 (a2w cols)); Ktot = a1w + a2w (A2 may be null).
// W "std": [N][Ktot][128]; W "headpacked": [HEADS][HID][AD] viewed as [Ktot][128]
// with col c -> Wk[c>>5][k][c&31]. Output always 128 wide.
// Tile: BM=128 x BN=128, KT=16, 256 threads, 8x8 micro-tile per thread.
__global__ void gemm128(const float* __restrict__ A1, int a1w,
                        const float* __restrict__ A2, int a2w,
                        const float* __restrict__ W, int headpacked,
                        const float* __restrict__ bias, int dorelu,
                        float* __restrict__ C, int Ktot)
{
    const int BM = 128, KT = 16, ASTR = BM + 4;  // padded stride vs bank conflicts
    __shared__ float As[KT * ASTR];
    __shared__ float Wsh[KT * 128];

    int n  = blockIdx.z;
    int b0 = blockIdx.x * BM;
    const float* A1n = A1 + (size_t)n * BATCH * a1w;
    const float* A2n = A2 ? (A2 + (size_t)n * BATCH * a2w) : A1;
    const float* Wn  = headpacked ? W : (W + (size_t)n * Ktot * 128);
    const float* bn  = bias ? (headpacked ? bias : bias + n * 128) : nullptr;
    float* Cn = C + (size_t)n * BATCH * 128;

    int tid  = threadIdx.x;
    int r0   = (tid >> 4) << 3;      // 0,8,...,120
    int c0   = (tid & 15) << 3;      // 0,8,...,120
    int arow = tid >> 2;             // 0..63
    int ak   = (tid & 3) << 2;       // 0,4,8,12
    int wrow = tid >> 4;             // 0..15
    int wcol = (tid & 15) << 3;      // 0..120

    float acc[8][8];
    #pragma unroll
    for (int i = 0; i < 8; i++)
        #pragma unroll
        for (int j = 0; j < 8; j++) acc[i][j] = 0.f;

    for (int k0 = 0; k0 < Ktot; k0 += KT) {
        // ---- stage A slab [BM x KT], stored transposed As[k][m] ----
        const float* src; int srcw, kbase;
        if (k0 < a1w) { src = A1n; srcw = a1w; kbase = k0; }
        else          { src = A2n; srcw = a2w; kbase = k0 - a1w; }
        #pragma unroll
        for (int s = 0; s < 2; s++) {
            int row = arow + s * 64;
            float4 v = *(const float4*)(src + (size_t)(b0 + row) * srcw + kbase + ak);
            As[(ak + 0) * ASTR + row] = v.x;
            As[(ak + 1) * ASTR + row] = v.y;
            As[(ak + 2) * ASTR + row] = v.z;
            As[(ak + 3) * ASTR + row] = v.w;
        }
        // ---- stage W slab [KT x 128] ----
        {
            const float* wp;
            if (!headpacked)
                wp = Wn + (size_t)(k0 + wrow) * 128 + wcol;
            else
                wp = Wn + (size_t)(wcol >> 5) * (HID * AD) + (size_t)(k0 + wrow) * AD + (wcol & 31);
            float4 w0 = *(const float4*)wp;
            float4 w1 = *(const float4*)(wp + 4);
            *(float4*)&Wsh[wrow * 128 + wcol]     = w0;
            *(float4*)&Wsh[wrow * 128 + wcol + 4] = w1;
        }
        __syncthreads();
        #pragma unroll
        for (int kk = 0; kk < KT; kk++) {
            float a[8], w[8];
            *(float4*)&a[0] = *(const float4*)&As[kk * ASTR + r0];
            *(float4*)&a[4] = *(const float4*)&As[kk * ASTR + r0 + 4];
            *(float4*)&w[0] = *(const float4*)&Wsh[kk * 128 + c0];
            *(float4*)&w[4] = *(const float4*)&Wsh[kk * 128 + c0 + 4];
            #pragma unroll
            for (int i = 0; i < 8; i++)
                #pragma unroll
                for (int j = 0; j < 8; j++)
                    acc[i][j] += a[i] * w[j];
        }
        __syncthreads();
    }

    float bvv[8];
    #pragma unroll
    for (int j = 0; j < 8; j++) bvv[j] = bn ? bn[c0 + j] : 0.f;
    #pragma unroll
    for (int i = 0; i < 8; i++) {
        float o[8];
        #pragma unroll
        for (int j = 0; j < 8; j++) {
            float v = acc[i][j] + bvv[j];
            o[j] = dorelu ? fmaxf(v, 0.f) : v;
        }
        size_t off = (size_t)(b0 + r0 + i) * 128 + c0;
        *(float4*)&Cn[off]     = *(float4*)&o[0];
        *(float4*)&Cn[off + 4] = *(float4*)&o[4];
    }
}

// ---------------- attention: other[i,b,k*32+d] = sum_j softmax_j(Q_i.K_j) V_j ----
// Block = 4 batch rows, 128 threads: thread (r = tid/32, head k = (tid/8)&3, agent i = tid&7)
__global__ void attn_kernel()
{
    __shared__ float Ks[4 * 8 * 128];   // [r][j][c]
    __shared__ float Vs[4 * 8 * 128];
    int tid = threadIdx.x;
    int b0  = blockIdx.x * 4;

    #pragma unroll
    for (int t = 0; t < 8; t++) {
        int f  = tid + t * 128;          // float4 index, 1024 total per array
        int c4 = f & 31;
        int r  = (f >> 5) & 3;
        int j  = f >> 7;
        size_t g = ((size_t)j * BATCH + b0 + r) * 128 + c4 * 4;
        int s = (r * 8 + j) * 128 + c4 * 4;
        *(float4*)&Ks[s] = *(const float4*)&g_Kb[g];
        *(float4*)&Vs[s] = *(const float4*)&g_Vb[g];
    }
    __syncthreads();

    int r = tid >> 5, k = (tid >> 3) & 3, i = tid & 7;
    float q[32];
    size_t base = ((size_t)i * BATCH + b0 + r) * 128 + k * 32;
    #pragma unroll
    for (int t = 0; t < 8; t++)
        *(float4*)&q[t * 4] = *(const float4*)&g_Qb[base + t * 4];

    float lg[8];
    #pragma unroll
    for (int j = 0; j < 8; j++) {
        const float* kp = &Ks[(r * 8 + j) * 128 + k * 32];
        float d = 0.f;
        #pragma unroll
        for (int dd = 0; dd < 32; dd++) d += q[dd] * kp[dd];
        lg[j] = (j == i) ? -1e9f : d * 0.17677669529663687f;  // 1/sqrt(32); self mask
    }
    float m = lg[0];
    #pragma unroll
    for (int j = 1; j < 8; j++) m = fmaxf(m, lg[j]);
    float ssum = 0.f;
    #pragma unroll
    for (int j = 0; j < 8; j++) { lg[j] = expf(lg[j] - m); ssum += lg[j]; }
    float inv = 1.f / ssum;

    float acc[32];
    #pragma unroll
    for (int dd = 0; dd < 32; dd++) acc[dd] = 0.f;
    #pragma unroll
    for (int j = 0; j < 8; j++) {
        float p = lg[j] * inv;
        const float* vp = &Vs[(r * 8 + j) * 128 + k * 32];
        #pragma unroll
        for (int dd = 0; dd < 32; dd++) acc[dd] += p * vp[dd];
    }
    #pragma unroll
    for (int t = 0; t < 8; t++)
        *(float4*)&g_oth[base + t * 4] = *(float4*)&acc[t * 4];
}

// ---------------- fused critic head -----------------------------------------------
// h1 = relu([s_enc | other] @ Wc1 + bc1)  (K=256 GEMM, BM=64 tile, h1 stays in smem)
// all_q = h1 @ Wc2 + bc2 ; out = all_q[argmax(actions)]
__global__ void critic_kernel(const float* __restrict__ actions,
                              const float* __restrict__ Wc1, const float* __restrict__ bc1,
                              const float* __restrict__ Wc2, const float* __restrict__ bc2,
                              float* __restrict__ out)
{
    const int BM = 64, KT = 16, ASTR = BM + 4;      // 68
    __shared__ float smU[64 * 129];                  // union: As(1088)+Ws(2048) | h1s(8256)
    __shared__ float Wc2s[128 * 16];
    __shared__ float bc2s[16];
    __shared__ int   amaxs[64];

    float* As  = smU;
    float* Wsh = smU + KT * ASTR;   // +1088
    float* h1s = smU;               // reused after main loop

    int n   = blockIdx.z;
    int b0  = blockIdx.x * BM;
    int tid = threadIdx.x;

    const float* Wc1n = Wc1 + (size_t)n * 256 * 128;
    const float* bc1n = bc1 + n * 128;
    const float* Wc2n = Wc2 + (size_t)n * 128 * 16;
    const float* Sn   = g_se  + (size_t)n * BATCH * 128;
    const float* On   = g_oth + (size_t)n * BATCH * 128;

    // stage Wc2 / bc2 / per-row argmax(actions)
    #pragma unroll
    for (int t = 0; t < 2; t++) {
        int f = tid + t * 256;   // 512 float4s
        *(float4*)&Wc2s[f * 4] = *(const float4*)&Wc2n[f * 4];
    }
    if (tid < 16) bc2s[tid] = bc2[n * 16 + tid];
    if (tid < 64) {
        const float* ap = actions + ((size_t)n * BATCH + b0 + tid) * 16;
        float best = ap[0]; int bi = 0;
        #pragma unroll
        for (int c = 1; c < 16; c++) { float v = ap[c]; if (v > best) { best = v; bi = c; } }
        amaxs[tid] = bi;
    }

    int r0   = (tid >> 4) << 2;   // 0..60
    int c0   = (tid & 15) << 3;
    int arow = tid >> 2;          // 0..63
    int ak   = (tid & 3) << 2;
    int wrow = tid >> 4;
    int wcol = (tid & 15) << 3;

    float acc[4][8];
    #pragma unroll
    for (int i = 0; i < 4; i++)
        #pragma unroll
        for (int j = 0; j < 8; j++) acc[i][j] = 0.f;

    for (int k0 = 0; k0 < 256; k0 += KT) {
        const float* src = (k0 < 128) ? Sn : On;
        int kbase = (k0 < 128) ? k0 : (k0 - 128);
        {
            float4 v = *(const float4*)(src + (size_t)(b0 + arow) * 128 + kbase + ak);
            As[(ak + 0) * ASTR + arow] = v.x;
            As[(ak + 1) * ASTR + arow] = v.y;
            As[(ak + 2) * ASTR + arow] = v.z;
            As[(ak + 3) * ASTR + arow] = v.w;
        }
        {
            const float* wp = Wc1n + (size_t)(k0 + wrow) * 128 + wcol;
            float4 w0 = *(const float4*)wp;
            float4 w1 = *(const float4*)(wp + 4);
            *(float4*)&Wsh[wrow * 128 + wcol]     = w0;
            *(float4*)&Wsh[wrow * 128 + wcol + 4] = w1;
        }
        __syncthreads();
        #pragma unroll
        for (int kk = 0; kk < KT; kk++) {
            float a[4], w[8];
            *(float4*)&a[0] = *(const float4*)&As[kk * ASTR + r0];
            *(float4*)&w[0] = *(const float4*)&Wsh[kk * 128 + c0];
            *(float4*)&w[4] = *(const float4*)&Wsh[kk * 128 + c0 + 4];
            #pragma unroll
            for (int i = 0; i < 4; i++)
                #pragma unroll
                for (int j = 0; j < 8; j++)
                    acc[i][j] += a[i] * w[j];
        }
        __syncthreads();
    }

    // h1 (bias + relu) into smem union (safe: last loop iter ended with a barrier)
    #pragma unroll
    for (int i = 0; i < 4; i++)
        #pragma unroll
        for (int j = 0; j < 8; j++) {
            float v = acc[i][j] + bc1n[c0 + j];
            h1s[(r0 + i) * 129 + c0 + j] = fmaxf(v, 0.f);
        }
    __syncthreads();

    // all_q tile: 64 rows x 16 cols, thread -> (row = tid/4, 4 cols)
    int row2 = tid >> 2;
    int cg   = (tid & 3) << 2;
    float acc2[4] = {0.f, 0.f, 0.f, 0.f};
    for (int h = 0; h < 128; h++) {
        float hv = h1s[row2 * 129 + h];
        #pragma unroll
        for (int j = 0; j < 4; j++) acc2[j] += hv * Wc2s[h * 16 + cg + j];
    }
    int a = amaxs[row2];
    #pragma unroll
    for (int j = 0; j < 4; j++)
        if (cg + j == a)
            out[(size_t)n * BATCH + b0 + row2] = acc2[j] + bc2s[a];
}

// ---------------- launch -----------------------------------------------------------
extern "C" void kernel_launch(void* const* d_in, const int* in_sizes, int n_in,
                              void* d_out, int out_size)
{
    const float* states  = (const float*)d_in[0];
    const float* actions = (const float*)d_in[1];
    const float* We      = (const float*)d_in[2];
    const float* be      = (const float*)d_in[3];
    const float* Wse     = (const float*)d_in[4];
    const float* bs      = (const float*)d_in[5];
    const float* Wk      = (const float*)d_in[6];
    const float* Wq      = (const float*)d_in[7];
    const float* Wv      = (const float*)d_in[8];
    const float* bv      = (const float*)d_in[9];
    const float* Wc1     = (const float*)d_in[10];
    const float* bc1     = (const float*)d_in[11];
    const float* Wc2     = (const float*)d_in[12];
    const float* bc2     = (const float*)d_in[13];
    float* out = (float*)d_out;

    float *p_sa, *p_se, *p_K, *p_Q, *p_V;
    cudaGetSymbolAddress((void**)&p_sa, g_sa);
    cudaGetSymbolAddress((void**)&p_se, g_se);
    cudaGetSymbolAddress((void**)&p_K,  g_Kb);
    cudaGetSymbolAddress((void**)&p_Q,  g_Qb);
    cudaGetSymbolAddress((void**)&p_V,  g_Vb);

    dim3 grid(BATCH / 128, 1, NAG);
    // encoders
    gemm128<<<grid, 256>>>(states, SDIM, actions, ADIM, We, 0, be, 1, p_sa, SDIM + ADIM);
    gemm128<<<grid, 256>>>(states, SDIM, nullptr, 0,    Wse, 0, bs, 1, p_se, SDIM);
    // per-head projections (heads concatenated along output cols)
    gemm128<<<grid, 256>>>(p_sa, HID, nullptr, 0, Wk, 1, nullptr, 0, p_K, HID);
    gemm128<<<grid, 256>>>(p_se, HID, nullptr, 0, Wq, 1, nullptr, 0, p_Q, HID);
    gemm128<<<grid, 256>>>(p_sa, HID, nullptr, 0, Wv, 1, bv,      1, p_V, HID);
    // attention
    attn_kernel<<<BATCH / 4, 128>>>();
    // critic MLP + gather
    critic_kernel<<<dim3(BATCH / 64, 1, NAG), 256>>>(actions, Wc1, bc1, Wc2, bc2, out);
}

// round 2
// speedup vs baseline: 1.0303x; 1.0303x over previous
#include <cuda_runtime.h>
#include <cstdint>

#define NAG   8
#define BATCH 32768
#define SDIM  128
#define ADIM  16
#define HID   128
#define HEADS 4
#define AD    32

typedef unsigned long long ull;

// ---------------- scratch (device globals; no allocation allowed) ----------------
__device__ float g_sa   [(size_t)NAG * BATCH * HID];   // sa_enc
__device__ float g_se   [(size_t)NAG * BATCH * HID];   // s_enc
__device__ float g_Kb   [(size_t)NAG * BATCH * HID];   // K  [n][b][k*32+d]
__device__ float g_Qb   [(size_t)NAG * BATCH * HID];   // Q
__device__ float g_Vb   [(size_t)NAG * BATCH * HID];   // V
__device__ float g_oth  [(size_t)NAG * BATCH * HID];   // attention output
__device__ float g_h1   [(size_t)NAG * BATCH * HID];   // critic hidden

// ---------------- per-agent SGEMM with packed f32x2 FMA ---------------------------
// C[n] = act(A[n] @ W[n] + b[n]);  A = concat(A1 (a1w), A2 (a2w)); out width 128.
// W std: [N][Ktot][128]; headpacked: [HEADS][HID][AD] viewed as [Ktot][128].
// Tile BM=128 x BN=128, KT=16, 256 threads, 8x8 micro-tile (as 8 rows x 4 col-pairs).
// A slab stored DUPLICATED ({v,v}) so broadcast operand loads as 64-bit packs.
__global__ void __launch_bounds__(256, 2)
gemm128(const float* __restrict__ A1, int a1w,
        const float* __restrict__ A2, int a2w,
        const float* __restrict__ W, int headpacked,
        const float* __restrict__ bias, int dorelu,
        float* __restrict__ C, int Ktot)
{
    const int BM = 128, KT = 16, ASTR2 = 2 * BM + 4;   // 260 words, 16B-aligned rows
    __shared__ float Asd[KT * ASTR2];                  // duplicated A, [k][2m..2m+1]
    __shared__ float Wsh[KT * 128];

    int n  = blockIdx.z;
    int b0 = blockIdx.x * BM;
    const float* A1n = A1 + (size_t)n * BATCH * a1w;
    const float* A2n = A2 ? (A2 + (size_t)n * BATCH * a2w) : A1;
    const float* Wn  = headpacked ? W : (W + (size_t)n * Ktot * 128);
    const float* bn  = bias ? (headpacked ? bias : bias + n * 128) : nullptr;
    float* Cn = C + (size_t)n * BATCH * 128;

    int tid  = threadIdx.x;
    int r0   = (tid >> 4) << 3;      // 0,8,...,120
    int c0   = (tid & 15) << 3;      // 0,8,...,120
    int arow = tid >> 2;             // 0..63
    int ak   = (tid & 3) << 2;       // 0,4,8,12
    int wrow = tid >> 4;             // 0..15
    int wcol = (tid & 15) << 3;      // 0..120

    ull acc[8][4];
    #pragma unroll
    for (int i = 0; i < 8; i++)
        #pragma unroll
        for (int jp = 0; jp < 4; jp++) acc[i][jp] = 0ULL;

    for (int k0 = 0; k0 < Ktot; k0 += KT) {
        // ---- stage A slab [BM x KT] transposed + duplicated: Asd[k][2m]={v,v} ----
        const float* src; int srcw, kbase;
        if (k0 < a1w) { src = A1n; srcw = a1w; kbase = k0; }
        else          { src = A2n; srcw = a2w; kbase = k0 - a1w; }
        #pragma unroll
        for (int s = 0; s < 2; s++) {
            int row = arow + s * 64;
            float4 v = *(const float4*)(src + (size_t)(b0 + row) * srcw + kbase + ak);
            *(float2*)&Asd[(ak + 0) * ASTR2 + 2 * row] = make_float2(v.x, v.x);
            *(float2*)&Asd[(ak + 1) * ASTR2 + 2 * row] = make_float2(v.y, v.y);
            *(float2*)&Asd[(ak + 2) * ASTR2 + 2 * row] = make_float2(v.z, v.z);
            *(float2*)&Asd[(ak + 3) * ASTR2 + 2 * row] = make_float2(v.w, v.w);
        }
        // ---- stage W slab [KT x 128] ----
        {
            const float* wp;
            if (!headpacked)
                wp = Wn + (size_t)(k0 + wrow) * 128 + wcol;
            else
                wp = Wn + (size_t)(wcol >> 5) * (HID * AD) + (size_t)(k0 + wrow) * AD + (wcol & 31);
            float4 w0 = *(const float4*)wp;
            float4 w1 = *(const float4*)(wp + 4);
            *(float4*)&Wsh[wrow * 128 + wcol]     = w0;
            *(float4*)&Wsh[wrow * 128 + wcol + 4] = w1;
        }
        __syncthreads();
        #pragma unroll
        for (int kk = 0; kk < KT; kk++) {
            // a dup-packs: 16 consecutive floats (broadcast within 16-lane groups)
            const ulonglong2* av = (const ulonglong2*)&Asd[kk * ASTR2 + 2 * r0];
            ulonglong2 a01 = av[0], a23 = av[1], a45 = av[2], a67 = av[3];
            ull ap[8] = {a01.x, a01.y, a23.x, a23.y, a45.x, a45.y, a67.x, a67.y};
            // w pair-packs: 8 consecutive floats = 4 pairs
            const ulonglong2* wv = (const ulonglong2*)&Wsh[kk * 128 + c0];
            ulonglong2 w01 = wv[0], w23 = wv[1];
            ull wp[4] = {w01.x, w01.y, w23.x, w23.y};
            #pragma unroll
            for (int i = 0; i < 8; i++)
                #pragma unroll
                for (int jp = 0; jp < 4; jp++)
                    asm("fma.rn.f32x2 %0, %1, %2, %0;"
                        : "+l"(acc[i][jp]) : "l"(ap[i]), "l"(wp[jp]));
        }
        __syncthreads();
    }

    float bvv[8];
    #pragma unroll
    for (int j = 0; j < 8; j++) bvv[j] = bn ? bn[c0 + j] : 0.f;
    #pragma unroll
    for (int i = 0; i < 8; i++) {
        float o[8];
        #pragma unroll
        for (int jp = 0; jp < 4; jp++) {
            float lo = __uint_as_float((unsigned)(acc[i][jp] & 0xffffffffULL));
            float hi = __uint_as_float((unsigned)(acc[i][jp] >> 32));
            float v0 = lo + bvv[2 * jp];
            float v1 = hi + bvv[2 * jp + 1];
            o[2 * jp]     = dorelu ? fmaxf(v0, 0.f) : v0;
            o[2 * jp + 1] = dorelu ? fmaxf(v1, 0.f) : v1;
        }
        size_t off = (size_t)(b0 + r0 + i) * 128 + c0;
        *(float4*)&Cn[off]     = *(float4*)&o[0];
        *(float4*)&Cn[off + 4] = *(float4*)&o[4];
    }
}

// ---------------- attention: other[i,b,k*32+d] = sum_j softmax_j(Q_i.K_j) V_j ----
__global__ void attn_kernel()
{
    __shared__ float Ks[4 * 8 * 128];   // [r][j][c]
    __shared__ float Vs[4 * 8 * 128];
    int tid = threadIdx.x;
    int b0  = blockIdx.x * 4;

    #pragma unroll
    for (int t = 0; t < 8; t++) {
        int f  = tid + t * 128;          // float4 index
        int c4 = f & 31;
        int r  = (f >> 5) & 3;
        int j  = f >> 7;
        size_t g = ((size_t)j * BATCH + b0 + r) * 128 + c4 * 4;
        int s = (r * 8 + j) * 128 + c4 * 4;
        *(float4*)&Ks[s] = *(const float4*)&g_Kb[g];
        *(float4*)&Vs[s] = *(const float4*)&g_Vb[g];
    }
    __syncthreads();

    int r = tid >> 5, k = (tid >> 3) & 3, i = tid & 7;
    float q[32];
    size_t base = ((size_t)i * BATCH + b0 + r) * 128 + k * 32;
    #pragma unroll
    for (int t = 0; t < 8; t++)
        *(float4*)&q[t * 4] = *(const float4*)&g_Qb[base + t * 4];

    float lg[8];
    #pragma unroll
    for (int j = 0; j < 8; j++) {
        const float* kp = &Ks[(r * 8 + j) * 128 + k * 32];
        float d = 0.f;
        #pragma unroll
        for (int dd = 0; dd < 32; dd++) d += q[dd] * kp[dd];
        lg[j] = (j == i) ? -1e9f : d * 0.17677669529663687f;
    }
    float m = lg[0];
    #pragma unroll
    for (int j = 1; j < 8; j++) m = fmaxf(m, lg[j]);
    float ssum = 0.f;
    #pragma unroll
    for (int j = 0; j < 8; j++) { lg[j] = __expf(lg[j] - m); ssum += lg[j]; }
    float inv = 1.f / ssum;

    float acc[32];
    #pragma unroll
    for (int dd = 0; dd < 32; dd++) acc[dd] = 0.f;
    #pragma unroll
    for (int j = 0; j < 8; j++) {
        float p = lg[j] * inv;
        const float* vp = &Vs[(r * 8 + j) * 128 + k * 32];
        #pragma unroll
        for (int dd = 0; dd < 32; dd++) acc[dd] += p * vp[dd];
    }
    #pragma unroll
    for (int t = 0; t < 8; t++)
        *(float4*)&g_oth[base + t * 4] = *(float4*)&acc[t * 4];
}

// ---------------- all_q + argmax gather -------------------------------------------
// out[n,b] = dot(h1[n,b,:], Wc2[n,:,a]) + bc2[n,a],  a = argmax(actions[n,b,:])
__global__ void allq_kernel(const float* __restrict__ actions,
                            const float* __restrict__ Wc2,
                            const float* __restrict__ bc2,
                            float* __restrict__ out)
{
    __shared__ float Wc2s[128 * 16];
    __shared__ float bc2s[16];
    int n = blockIdx.z;
    int b0 = blockIdx.x * 256;
    int tid = threadIdx.x;
    const float* Wc2n = Wc2 + (size_t)n * 128 * 16;

    #pragma unroll
    for (int t = 0; t < 2; t++) {
        int f = tid + t * 256;
        *(float4*)&Wc2s[f * 4] = *(const float4*)&Wc2n[f * 4];
    }
    if (tid < 16) bc2s[tid] = bc2[n * 16 + tid];
    __syncthreads();

    int b = b0 + tid;
    const float* ap = actions + ((size_t)n * BATCH + b) * 16;
    float best = ap[0]; int a = 0;
    #pragma unroll
    for (int c = 1; c < 16; c++) { float v = ap[c]; if (v > best) { best = v; a = c; } }

    const float* hp = g_h1 + ((size_t)n * BATCH + b) * 128;
    float acc = 0.f;
    #pragma unroll
    for (int h4 = 0; h4 < 128; h4 += 4) {
        float4 hv = *(const float4*)&hp[h4];
        acc += hv.x * Wc2s[(h4 + 0) * 16 + a];
        acc += hv.y * Wc2s[(h4 + 1) * 16 + a];
        acc += hv.z * Wc2s[(h4 + 2) * 16 + a];
        acc += hv.w * Wc2s[(h4 + 3) * 16 + a];
    }
    out[(size_t)n * BATCH + b] = acc + bc2s[a];
}

// ---------------- launch -----------------------------------------------------------
extern "C" void kernel_launch(void* const* d_in, const int* in_sizes, int n_in,
                              void* d_out, int out_size)
{
    const float* states  = (const float*)d_in[0];
    const float* actions = (const float*)d_in[1];
    const float* We      = (const float*)d_in[2];
    const float* be      = (const float*)d_in[3];
    const float* Wse     = (const float*)d_in[4];
    const float* bs      = (const float*)d_in[5];
    const float* Wk      = (const float*)d_in[6];
    const float* Wq      = (const float*)d_in[7];
    const float* Wv      = (const float*)d_in[8];
    const float* bv      = (const float*)d_in[9];
    const float* Wc1     = (const float*)d_in[10];
    const float* bc1     = (const float*)d_in[11];
    const float* Wc2     = (const float*)d_in[12];
    const float* bc2     = (const float*)d_in[13];
    float* out = (float*)d_out;

    float *p_sa, *p_se, *p_K, *p_Q, *p_V, *p_oth, *p_h1;
    cudaGetSymbolAddress((void**)&p_sa,  g_sa);
    cudaGetSymbolAddress((void**)&p_se,  g_se);
    cudaGetSymbolAddress((void**)&p_K,   g_Kb);
    cudaGetSymbolAddress((void**)&p_Q,   g_Qb);
    cudaGetSymbolAddress((void**)&p_V,   g_Vb);
    cudaGetSymbolAddress((void**)&p_oth, g_oth);
    cudaGetSymbolAddress((void**)&p_h1,  g_h1);

    dim3 grid(BATCH / 128, 1, NAG);
    // encoders
    gemm128<<<grid, 256>>>(states, SDIM, actions, ADIM, We, 0, be, 1, p_sa, SDIM + ADIM);
    gemm128<<<grid, 256>>>(states, SDIM, nullptr, 0,    Wse, 0, bs, 1, p_se, SDIM);
    // per-head projections
    gemm128<<<grid, 256>>>(p_sa, HID, nullptr, 0, Wk, 1, nullptr, 0, p_K, HID);
    gemm128<<<grid, 256>>>(p_se, HID, nullptr, 0, Wq, 1, nullptr, 0, p_Q, HID);
    gemm128<<<grid, 256>>>(p_sa, HID, nullptr, 0, Wv, 1, bv,      1, p_V, HID);
    // attention
    attn_kernel<<<BATCH / 4, 128>>>();
    // critic hidden: h1 = relu([s_enc | other] @ Wc1 + bc1), K=256
    gemm128<<<grid, 256>>>(p_se, HID, p_oth, HID, Wc1, 0, bc1, 1, p_h1, 2 * HID);
    // all_q + gather
    allq_kernel<<<dim3(BATCH / 256, 1, NAG), 256>>>(actions, Wc2, bc2, out);
}

// round 3
// speedup vs baseline: 2.1309x; 2.0683x over previous
#include <cuda_runtime.h>
#include <cstdint>

#define NAG   8
#define BATCH 32768
#define SDIM  128
#define ADIM  16
#define HID   128
#define HEADS 4
#define AD    32

// ---------------- scratch (device globals; no allocation allowed) ----------------
__device__ float g_sa   [(size_t)NAG * BATCH * HID];
__device__ float g_se   [(size_t)NAG * BATCH * HID];
__device__ float g_Kb   [(size_t)NAG * BATCH * HID];
__device__ float g_Qb   [(size_t)NAG * BATCH * HID];
__device__ float g_Vb   [(size_t)NAG * BATCH * HID];
__device__ float g_oth  [(size_t)NAG * BATCH * HID];
__device__ float g_h1   [(size_t)NAG * BATCH * HID];

__device__ __forceinline__ unsigned totf32(float x) {
    unsigned u;
    asm("cvt.rna.tf32.f32 %0, %1;" : "=r"(u) : "f"(x));
    return u;
}

// ---------------- per-agent GEMM on tensor cores (tf32, fp32 accumulate) ----------
// C[n] = act(A[n] @ W[n] + b[n]);  A = concat(A1 (a1w), A2 (a2w)); out width 128.
// W std: [N][Ktot][128]; headpacked: [HEADS][HID][AD] viewed as [Ktot][128].
// Block 128x128, 8 warps (2x4), warp tile 64x32 = 4x4 m16n8k8 mma tiles.
// Smem: A transposed [k][m] stride 132, W [k][n] stride 132, double buffered.
__global__ void __launch_bounds__(256)
gemm128_tc(const float* __restrict__ A1, int a1w,
           const float* __restrict__ A2, int a2w,
           const float* __restrict__ W, int headpacked,
           const float* __restrict__ bias, int dorelu,
           float* __restrict__ C, int Ktot)
{
    const int KT = 16, STR = 132;
    __shared__ unsigned As[2][KT * STR];
    __shared__ unsigned Bs[2][KT * STR];

    int n   = blockIdx.z;
    int b0g = blockIdx.x * 128;
    const float* A1n = A1 + (size_t)n * BATCH * a1w;
    const float* A2n = A2 ? (A2 + (size_t)n * BATCH * a2w) : A1;
    const float* Wn  = headpacked ? W : (W + (size_t)n * Ktot * 128);
    const float* bn  = bias ? (headpacked ? bias : bias + n * 128) : nullptr;
    float* Cn = C + (size_t)n * BATCH * 128;

    int tid  = threadIdx.x;
    int wid  = tid >> 5, lane = tid & 31;
    int grp  = lane >> 2, tig = lane & 3;
    int wm   = (wid >> 2) * 64;       // warp m base (0 / 64)
    int wn   = (wid & 3) * 32;        // warp n base (0/32/64/96)

    // staging thread mapping
    int arow = tid >> 2;              // 0..63 (two rows: +0, +64)
    int ak   = (tid & 3) << 2;        // 0,4,8,12
    int krow = tid >> 4;              // 0..15
    int wcol = (tid & 15) << 3;       // 0..120

    float acc[4][4][4];
    #pragma unroll
    for (int mt = 0; mt < 4; mt++)
        #pragma unroll
        for (int nt = 0; nt < 4; nt++)
            #pragma unroll
            for (int r = 0; r < 4; r++) acc[mt][nt][r] = 0.f;

    int nkt = Ktot >> 4;
    float4 va0, va1, vw0, vw1;

    // ---- load k-tile kt into registers ----
    auto ldtile = [&](int kt) {
        int k0 = kt * KT;
        const float* src; int srcw, kbase;
        if (k0 < a1w) { src = A1n; srcw = a1w; kbase = k0; }
        else          { src = A2n; srcw = a2w; kbase = k0 - a1w; }
        va0 = *(const float4*)(src + (size_t)(b0g + arow)      * srcw + kbase + ak);
        va1 = *(const float4*)(src + (size_t)(b0g + arow + 64) * srcw + kbase + ak);
        const float* wp;
        if (!headpacked) wp = Wn + (size_t)(k0 + krow) * 128 + wcol;
        else             wp = Wn + (size_t)(wcol >> 5) * (HID * AD) + (size_t)(k0 + krow) * AD + (wcol & 31);
        vw0 = *(const float4*)wp;
        vw1 = *(const float4*)(wp + 4);
    };
    // ---- convert + store registers to smem buffer ----
    auto ststile = [&](int buf) {
        unsigned* Ab = As[buf];
        Ab[(ak + 0) * STR + arow]      = totf32(va0.x);
        Ab[(ak + 1) * STR + arow]      = totf32(va0.y);
        Ab[(ak + 2) * STR + arow]      = totf32(va0.z);
        Ab[(ak + 3) * STR + arow]      = totf32(va0.w);
        Ab[(ak + 0) * STR + arow + 64] = totf32(va1.x);
        Ab[(ak + 1) * STR + arow + 64] = totf32(va1.y);
        Ab[(ak + 2) * STR + arow + 64] = totf32(va1.z);
        Ab[(ak + 3) * STR + arow + 64] = totf32(va1.w);
        uint4 w0 = { totf32(vw0.x), totf32(vw0.y), totf32(vw0.z), totf32(vw0.w) };
        uint4 w1 = { totf32(vw1.x), totf32(vw1.y), totf32(vw1.z), totf32(vw1.w) };
        *(uint4*)&Bs[buf][krow * STR + wcol]     = w0;
        *(uint4*)&Bs[buf][krow * STR + wcol + 4] = w1;
    };

    ldtile(0);
    ststile(0);
    __syncthreads();

    for (int kt = 0; kt < nkt; kt++) {
        int buf = kt & 1;
        if (kt + 1 < nkt) ldtile(kt + 1);

        #pragma unroll
        for (int ks = 0; ks < 2; ks++) {
            const unsigned* Ab = As[buf];
            const unsigned* Bb = Bs[buf];
            int kr0 = (ks * 8 + tig) * STR;
            int kr4 = (ks * 8 + tig + 4) * STR;
            unsigned af[4][4];
            #pragma unroll
            for (int mt = 0; mt < 4; mt++) {
                int m = wm + mt * 16 + grp;
                af[mt][0] = Ab[kr0 + m];
                af[mt][1] = Ab[kr0 + m + 8];
                af[mt][2] = Ab[kr4 + m];
                af[mt][3] = Ab[kr4 + m + 8];
            }
            unsigned bf[4][2];
            #pragma unroll
            for (int nt = 0; nt < 4; nt++) {
                int c = wn + nt * 8 + grp;
                bf[nt][0] = Bb[kr0 + c];
                bf[nt][1] = Bb[kr4 + c];
            }
            #pragma unroll
            for (int mt = 0; mt < 4; mt++)
                #pragma unroll
                for (int nt = 0; nt < 4; nt++)
                    asm("mma.sync.aligned.m16n8k8.row.col.f32.tf32.tf32.f32 "
                        "{%0,%1,%2,%3}, {%4,%5,%6,%7}, {%8,%9}, {%0,%1,%2,%3};"
                        : "+f"(acc[mt][nt][0]), "+f"(acc[mt][nt][1]),
                          "+f"(acc[mt][nt][2]), "+f"(acc[mt][nt][3])
                        : "r"(af[mt][0]), "r"(af[mt][1]), "r"(af[mt][2]), "r"(af[mt][3]),
                          "r"(bf[nt][0]), "r"(bf[nt][1]));
        }
        if (kt + 1 < nkt) ststile(buf ^ 1);
        __syncthreads();
    }

    // ---- epilogue: bias + relu + store ----
    #pragma unroll
    for (int nt = 0; nt < 4; nt++) {
        int col = wn + nt * 8 + tig * 2;
        float bj0 = bn ? bn[col]     : 0.f;
        float bj1 = bn ? bn[col + 1] : 0.f;
        #pragma unroll
        for (int mt = 0; mt < 4; mt++) {
            int row0 = b0g + wm + mt * 16 + grp;
            float v0 = acc[mt][nt][0] + bj0;
            float v1 = acc[mt][nt][1] + bj1;
            float v2 = acc[mt][nt][2] + bj0;
            float v3 = acc[mt][nt][3] + bj1;
            if (dorelu) {
                v0 = fmaxf(v0, 0.f); v1 = fmaxf(v1, 0.f);
                v2 = fmaxf(v2, 0.f); v3 = fmaxf(v3, 0.f);
            }
            *(float2*)&Cn[(size_t)row0 * 128 + col]       = make_float2(v0, v1);
            *(float2*)&Cn[(size_t)(row0 + 8) * 128 + col] = make_float2(v2, v3);
        }
    }
}

// ---------------- attention (exact fp32) ------------------------------------------
__global__ void attn_kernel()
{
    __shared__ float Ks[4 * 8 * 128];
    __shared__ float Vs[4 * 8 * 128];
    int tid = threadIdx.x;
    int b0  = blockIdx.x * 4;

    #pragma unroll
    for (int t = 0; t < 8; t++) {
        int f  = tid + t * 128;
        int c4 = f & 31;
        int r  = (f >> 5) & 3;
        int j  = f >> 7;
        size_t g = ((size_t)j * BATCH + b0 + r) * 128 + c4 * 4;
        int s = (r * 8 + j) * 128 + c4 * 4;
        *(float4*)&Ks[s] = *(const float4*)&g_Kb[g];
        *(float4*)&Vs[s] = *(const float4*)&g_Vb[g];
    }
    __syncthreads();

    int r = tid >> 5, k = (tid >> 3) & 3, i = tid & 7;
    float q[32];
    size_t base = ((size_t)i * BATCH + b0 + r) * 128 + k * 32;
    #pragma unroll
    for (int t = 0; t < 8; t++)
        *(float4*)&q[t * 4] = *(const float4*)&g_Qb[base + t * 4];

    float lg[8];
    #pragma unroll
    for (int j = 0; j < 8; j++) {
        const float* kp = &Ks[(r * 8 + j) * 128 + k * 32];
        float d = 0.f;
        #pragma unroll
        for (int dd = 0; dd < 32; dd++) d += q[dd] * kp[dd];
        lg[j] = (j == i) ? -1e9f : d * 0.17677669529663687f;
    }
    float m = lg[0];
    #pragma unroll
    for (int j = 1; j < 8; j++) m = fmaxf(m, lg[j]);
    float ssum = 0.f;
    #pragma unroll
    for (int j = 0; j < 8; j++) { lg[j] = __expf(lg[j] - m); ssum += lg[j]; }
    float inv = 1.f / ssum;

    float acc[32];
    #pragma unroll
    for (int dd = 0; dd < 32; dd++) acc[dd] = 0.f;
    #pragma unroll
    for (int j = 0; j < 8; j++) {
        float p = lg[j] * inv;
        const float* vp = &Vs[(r * 8 + j) * 128 + k * 32];
        #pragma unroll
        for (int dd = 0; dd < 32; dd++) acc[dd] += p * vp[dd];
    }
    #pragma unroll
    for (int t = 0; t < 8; t++)
        *(float4*)&g_oth[base + t * 4] = *(float4*)&acc[t * 4];
}

// ---------------- all_q + argmax gather (exact fp32) ------------------------------
__global__ void allq_kernel(const float* __restrict__ actions,
                            const float* __restrict__ Wc2,
                            const float* __restrict__ bc2,
                            float* __restrict__ out)
{
    __shared__ float Wc2s[128 * 16];
    __shared__ float bc2s[16];
    int n = blockIdx.z;
    int b0 = blockIdx.x * 256;
    int tid = threadIdx.x;
    const float* Wc2n = Wc2 + (size_t)n * 128 * 16;

    #pragma unroll
    for (int t = 0; t < 2; t++) {
        int f = tid + t * 256;
        *(float4*)&Wc2s[f * 4] = *(const float4*)&Wc2n[f * 4];
    }
    if (tid < 16) bc2s[tid] = bc2[n * 16 + tid];
    __syncthreads();

    int b = b0 + tid;
    const float* ap = actions + ((size_t)n * BATCH + b) * 16;
    float best = ap[0]; int a = 0;
    #pragma unroll
    for (int c = 1; c < 16; c++) { float v = ap[c]; if (v > best) { best = v; a = c; } }

    const float* hp = g_h1 + ((size_t)n * BATCH + b) * 128;
    float acc = 0.f;
    #pragma unroll
    for (int h4 = 0; h4 < 128; h4 += 4) {
        float4 hv = *(const float4*)&hp[h4];
        acc += hv.x * Wc2s[(h4 + 0) * 16 + a];
        acc += hv.y * Wc2s[(h4 + 1) * 16 + a];
        acc += hv.z * Wc2s[(h4 + 2) * 16 + a];
        acc += hv.w * Wc2s[(h4 + 3) * 16 + a];
    }
    out[(size_t)n * BATCH + b] = acc + bc2s[a];
}

// ---------------- launch -----------------------------------------------------------
extern "C" void kernel_launch(void* const* d_in, const int* in_sizes, int n_in,
                              void* d_out, int out_size)
{
    const float* states  = (const float*)d_in[0];
    const float* actions = (const float*)d_in[1];
    const float* We      = (const float*)d_in[2];
    const float* be      = (const float*)d_in[3];
    const float* Wse     = (const float*)d_in[4];
    const float* bs      = (const float*)d_in[5];
    const float* Wk      = (const float*)d_in[6];
    const float* Wq      = (const float*)d_in[7];
    const float* Wv      = (const float*)d_in[8];
    const float* bv      = (const float*)d_in[9];
    const float* Wc1     = (const float*)d_in[10];
    const float* bc1     = (const float*)d_in[11];
    const float* Wc2     = (const float*)d_in[12];
    const float* bc2     = (const float*)d_in[13];
    float* out = (float*)d_out;

    float *p_sa, *p_se, *p_K, *p_Q, *p_V, *p_oth, *p_h1;
    cudaGetSymbolAddress((void**)&p_sa,  g_sa);
    cudaGetSymbolAddress((void**)&p_se,  g_se);
    cudaGetSymbolAddress((void**)&p_K,   g_Kb);
    cudaGetSymbolAddress((void**)&p_Q,   g_Qb);
    cudaGetSymbolAddress((void**)&p_V,   g_Vb);
    cudaGetSymbolAddress((void**)&p_oth, g_oth);
    cudaGetSymbolAddress((void**)&p_h1,  g_h1);

    dim3 grid(BATCH / 128, 1, NAG);
    gemm128_tc<<<grid, 256>>>(states, SDIM, actions, ADIM, We, 0, be, 1, p_sa, SDIM + ADIM);
    gemm128_tc<<<grid, 256>>>(states, SDIM, nullptr, 0,    Wse, 0, bs, 1, p_se, SDIM);
    gemm128_tc<<<grid, 256>>>(p_sa, HID, nullptr, 0, Wk, 1, nullptr, 0, p_K, HID);
    gemm128_tc<<<grid, 256>>>(p_se, HID, nullptr, 0, Wq, 1, nullptr, 0, p_Q, HID);
    gemm128_tc<<<grid, 256>>>(p_sa, HID, nullptr, 0, Wv, 1, bv,      1, p_V, HID);
    attn_kernel<<<BATCH / 4, 128>>>();
    gemm128_tc<<<grid, 256>>>(p_se, HID, p_oth, HID, Wc1, 0, bc1, 1, p_h1, 2 * HID);
    allq_kernel<<<dim3(BATCH / 256, 1, NAG), 256>>>(actions, Wc2, bc2, out);
}

// round 4
// speedup vs baseline: 2.3367x; 1.0966x over previous
#include <cuda_runtime.h>
#include <cstdint>

#define NAG   8
#define BATCH 32768
#define SDIM  128
#define ADIM  16
#define HID   128
#define HEADS 4
#define AD    32

// ---------------- scratch (device globals; no allocation allowed) ----------------
__device__ float g_sa   [(size_t)NAG * BATCH * HID];
__device__ float g_se   [(size_t)NAG * BATCH * HID];
__device__ float g_Kb   [(size_t)NAG * BATCH * HID];
__device__ float g_Qb   [(size_t)NAG * BATCH * HID];
__device__ float g_Vb   [(size_t)NAG * BATCH * HID];
__device__ float g_oth  [(size_t)NAG * BATCH * HID];
__device__ float g_h1   [(size_t)NAG * BATCH * HID];

__device__ __forceinline__ unsigned totf32(float x) {
    unsigned u;
    asm("cvt.rna.tf32.f32 %0, %1;" : "=r"(u) : "f"(x));
    return u;
}

// A smem addressing: word = k*136 + 4*((k>>2)&1) + m  (conflict-free frag loads,
// bank = grp + 8*tig + const; 2-way store conflicts only).
__device__ __forceinline__ int AIDX(int k, int m) {
    return k * 136 + (((k >> 2) & 1) << 2) + m;
}
// B smem: word = k*136 + n (bank = grp + 8*tig + const on frag loads).
__device__ __forceinline__ int BIDX(int k, int n) {
    return k * 136 + n;
}

// ---------------- per-agent GEMM on tensor cores (tf32, fp32 accumulate) ----------
// C[n] = act(A[n] @ W[n] + b[n]);  A = concat(A1 (a1w), A2 (a2w)); out width 128.
// W std: [N][Ktot][128]; headpacked: [HEADS][HID][AD] viewed as [Ktot][128].
// Block 128x128, 8 warps (2x4), warp tile 64x32 = 4x4 m16n8k8 mma tiles.
__global__ void __launch_bounds__(256)
gemm128_tc(const float* __restrict__ A1, int a1w,
           const float* __restrict__ A2, int a2w,
           const float* __restrict__ W, int headpacked,
           const float* __restrict__ bias, int dorelu,
           float* __restrict__ C, int Ktot)
{
    const int KT = 16, TSZ = 16 * 136;   // 2176 words per tile buffer
    __shared__ unsigned As[2][TSZ];
    __shared__ unsigned Bs[2][TSZ];

    int n   = blockIdx.z;
    int b0g = blockIdx.x * 128;
    const float* A1n = A1 + (size_t)n * BATCH * a1w;
    const float* A2n = A2 ? (A2 + (size_t)n * BATCH * a2w) : A1;
    const float* Wn  = headpacked ? W : (W + (size_t)n * Ktot * 128);
    const float* bn  = bias ? (headpacked ? bias : bias + n * 128) : nullptr;
    float* Cn = C + (size_t)n * BATCH * 128;

    int tid  = threadIdx.x;
    int wid  = tid >> 5, lane = tid & 31;
    int grp  = lane >> 2, tig = lane & 3;
    int wm   = (wid >> 2) * 64;       // warp m base (0 / 64)
    int wn   = (wid & 3) * 32;        // warp n base (0/32/64/96)

    // staging thread mapping
    int arow = tid >> 2;              // 0..63 (rows arow, arow+64)
    int ak   = (tid & 3) << 2;        // 0,4,8,12
    int krow = tid >> 4;              // 0..15
    int wcol = (tid & 15) << 3;       // 0..120

    float acc[4][4][4];
    #pragma unroll
    for (int mt = 0; mt < 4; mt++)
        #pragma unroll
        for (int nt = 0; nt < 4; nt++)
            #pragma unroll
            for (int r = 0; r < 4; r++) acc[mt][nt][r] = 0.f;

    int nkt = Ktot >> 4;
    float4 va0, va1, vw0, vw1;

    auto ldtile = [&](int kt) {
        int k0 = kt * KT;
        const float* src; int srcw, kbase;
        if (k0 < a1w) { src = A1n; srcw = a1w; kbase = k0; }
        else          { src = A2n; srcw = a2w; kbase = k0 - a1w; }
        va0 = *(const float4*)(src + (size_t)(b0g + arow)      * srcw + kbase + ak);
        va1 = *(const float4*)(src + (size_t)(b0g + arow + 64) * srcw + kbase + ak);
        const float* wp;
        if (!headpacked) wp = Wn + (size_t)(k0 + krow) * 128 + wcol;
        else             wp = Wn + (size_t)(wcol >> 5) * (HID * AD) + (size_t)(k0 + krow) * AD + (wcol & 31);
        vw0 = *(const float4*)wp;
        vw1 = *(const float4*)(wp + 4);
    };
    auto ststile = [&](int buf) {
        unsigned* Ab = As[buf];
        Ab[AIDX(ak + 0, arow)]      = totf32(va0.x);
        Ab[AIDX(ak + 1, arow)]      = totf32(va0.y);
        Ab[AIDX(ak + 2, arow)]      = totf32(va0.z);
        Ab[AIDX(ak + 3, arow)]      = totf32(va0.w);
        Ab[AIDX(ak + 0, arow + 64)] = totf32(va1.x);
        Ab[AIDX(ak + 1, arow + 64)] = totf32(va1.y);
        Ab[AIDX(ak + 2, arow + 64)] = totf32(va1.z);
        Ab[AIDX(ak + 3, arow + 64)] = totf32(va1.w);
        unsigned* Bb = Bs[buf];
        uint4 w0 = { totf32(vw0.x), totf32(vw0.y), totf32(vw0.z), totf32(vw0.w) };
        uint4 w1 = { totf32(vw1.x), totf32(vw1.y), totf32(vw1.z), totf32(vw1.w) };
        *(uint4*)&Bb[BIDX(krow, wcol)]     = w0;
        *(uint4*)&Bb[BIDX(krow, wcol + 4)] = w1;
    };

    ldtile(0);
    ststile(0);
    __syncthreads();

    for (int kt = 0; kt < nkt; kt++) {
        int buf = kt & 1;
        if (kt + 1 < nkt) ldtile(kt + 1);

        const unsigned* Ab = As[buf];
        const unsigned* Bb = Bs[buf];
        #pragma unroll
        for (int ks = 0; ks < 2; ks++) {
            int k0r = ks * 8 + tig;       // khi = 0
            int k4r = ks * 8 + tig + 4;   // khi = 1
            unsigned af[4][4];
            #pragma unroll
            for (int mt = 0; mt < 4; mt++) {
                int m = wm + mt * 16 + grp;
                af[mt][0] = Ab[AIDX(k0r, m)];
                af[mt][1] = Ab[AIDX(k0r, m + 8)];
                af[mt][2] = Ab[AIDX(k4r, m)];
                af[mt][3] = Ab[AIDX(k4r, m + 8)];
            }
            unsigned bf[4][2];
            #pragma unroll
            for (int nt = 0; nt < 4; nt++) {
                int c = wn + nt * 8 + grp;
                bf[nt][0] = Bb[BIDX(k0r, c)];
                bf[nt][1] = Bb[BIDX(k4r, c)];
            }
            #pragma unroll
            for (int mt = 0; mt < 4; mt++)
                #pragma unroll
                for (int nt = 0; nt < 4; nt++)
                    asm("mma.sync.aligned.m16n8k8.row.col.f32.tf32.tf32.f32 "
                        "{%0,%1,%2,%3}, {%4,%5,%6,%7}, {%8,%9}, {%0,%1,%2,%3};"
                        : "+f"(acc[mt][nt][0]), "+f"(acc[mt][nt][1]),
                          "+f"(acc[mt][nt][2]), "+f"(acc[mt][nt][3])
                        : "r"(af[mt][0]), "r"(af[mt][1]), "r"(af[mt][2]), "r"(af[mt][3]),
                          "r"(bf[nt][0]), "r"(bf[nt][1]));
        }
        if (kt + 1 < nkt) ststile(buf ^ 1);
        __syncthreads();
    }

    // ---- epilogue: bias + relu + store ----
    #pragma unroll
    for (int nt = 0; nt < 4; nt++) {
        int col = wn + nt * 8 + tig * 2;
        float bj0 = bn ? bn[col]     : 0.f;
        float bj1 = bn ? bn[col + 1] : 0.f;
        #pragma unroll
        for (int mt = 0; mt < 4; mt++) {
            int row0 = b0g + wm + mt * 16 + grp;
            float v0 = acc[mt][nt][0] + bj0;
            float v1 = acc[mt][nt][1] + bj1;
            float v2 = acc[mt][nt][2] + bj0;
            float v3 = acc[mt][nt][3] + bj1;
            if (dorelu) {
                v0 = fmaxf(v0, 0.f); v1 = fmaxf(v1, 0.f);
                v2 = fmaxf(v2, 0.f); v3 = fmaxf(v3, 0.f);
            }
            *(float2*)&Cn[(size_t)row0 * 128 + col]       = make_float2(v0, v1);
            *(float2*)&Cn[(size_t)(row0 + 8) * 128 + col] = make_float2(v2, v3);
        }
    }
}

// ---------------- attention (exact fp32) ------------------------------------------
__global__ void attn_kernel()
{
    __shared__ float Ks[4 * 8 * 128];
    __shared__ float Vs[4 * 8 * 128];
    int tid = threadIdx.x;
    int b0  = blockIdx.x * 4;

    #pragma unroll
    for (int t = 0; t < 8; t++) {
        int f  = tid + t * 128;
        int c4 = f & 31;
        int r  = (f >> 5) & 3;
        int j  = f >> 7;
        size_t g = ((size_t)j * BATCH + b0 + r) * 128 + c4 * 4;
        int s = (r * 8 + j) * 128 + c4 * 4;
        *(float4*)&Ks[s] = *(const float4*)&g_Kb[g];
        *(float4*)&Vs[s] = *(const float4*)&g_Vb[g];
    }
    __syncthreads();

    int r = tid >> 5, k = (tid >> 3) & 3, i = tid & 7;
    float q[32];
    size_t base = ((size_t)i * BATCH + b0 + r) * 128 + k * 32;
    #pragma unroll
    for (int t = 0; t < 8; t++)
        *(float4*)&q[t * 4] = *(const float4*)&g_Qb[base + t * 4];

    float lg[8];
    #pragma unroll
    for (int j = 0; j < 8; j++) {
        const float* kp = &Ks[(r * 8 + j) * 128 + k * 32];
        float d = 0.f;
        #pragma unroll
        for (int dd = 0; dd < 32; dd++) d += q[dd] * kp[dd];
        lg[j] = (j == i) ? -1e9f : d * 0.17677669529663687f;
    }
    float m = lg[0];
    #pragma unroll
    for (int j = 1; j < 8; j++) m = fmaxf(m, lg[j]);
    float ssum = 0.f;
    #pragma unroll
    for (int j = 0; j < 8; j++) { lg[j] = __expf(lg[j] - m); ssum += lg[j]; }
    float inv = 1.f / ssum;

    float acc[32];
    #pragma unroll
    for (int dd = 0; dd < 32; dd++) acc[dd] = 0.f;
    #pragma unroll
    for (int j = 0; j < 8; j++) {
        float p = lg[j] * inv;
        const float* vp = &Vs[(r * 8 + j) * 128 + k * 32];
        #pragma unroll
        for (int dd = 0; dd < 32; dd++) acc[dd] += p * vp[dd];
    }
    #pragma unroll
    for (int t = 0; t < 8; t++)
        *(float4*)&g_oth[base + t * 4] = *(float4*)&acc[t * 4];
}

// ---------------- all_q + argmax gather (exact fp32) ------------------------------
__global__ void allq_kernel(const float* __restrict__ actions,
                            const float* __restrict__ Wc2,
                            const float* __restrict__ bc2,
                            float* __restrict__ out)
{
    __shared__ float Wc2s[128 * 16];
    __shared__ float bc2s[16];
    int n = blockIdx.z;
    int b0 = blockIdx.x * 256;
    int tid = threadIdx.x;
    const float* Wc2n = Wc2 + (size_t)n * 128 * 16;

    #pragma unroll
    for (int t = 0; t < 2; t++) {
        int f = tid + t * 256;
        *(float4*)&Wc2s[f * 4] = *(const float4*)&Wc2n[f * 4];
    }
    if (tid < 16) bc2s[tid] = bc2[n * 16 + tid];
    __syncthreads();

    int b = b0 + tid;
    const float* ap = actions + ((size_t)n * BATCH + b) * 16;
    float best = ap[0]; int a = 0;
    #pragma unroll
    for (int c = 1; c < 16; c++) { float v = ap[c]; if (v > best) { best = v; a = c; } }

    const float* hp = g_h1 + ((size_t)n * BATCH + b) * 128;
    float acc = 0.f;
    #pragma unroll
    for (int h4 = 0; h4 < 128; h4 += 4) {
        float4 hv = *(const float4*)&hp[h4];
        acc += hv.x * Wc2s[(h4 + 0) * 16 + a];
        acc += hv.y * Wc2s[(h4 + 1) * 16 + a];
        acc += hv.z * Wc2s[(h4 + 2) * 16 + a];
        acc += hv.w * Wc2s[(h4 + 3) * 16 + a];
    }
    out[(size_t)n * BATCH + b] = acc + bc2s[a];
}

// ---------------- launch -----------------------------------------------------------
extern "C" void kernel_launch(void* const* d_in, const int* in_sizes, int n_in,
                              void* d_out, int out_size)
{
    const float* states  = (const float*)d_in[0];
    const float* actions = (const float*)d_in[1];
    const float* We      = (const float*)d_in[2];
    const float* be      = (const float*)d_in[3];
    const float* Wse     = (const float*)d_in[4];
    const float* bs      = (const float*)d_in[5];
    const float* Wk      = (const float*)d_in[6];
    const float* Wq      = (const float*)d_in[7];
    const float* Wv      = (const float*)d_in[8];
    const float* bv      = (const float*)d_in[9];
    const float* Wc1     = (const float*)d_in[10];
    const float* bc1     = (const float*)d_in[11];
    const float* Wc2     = (const float*)d_in[12];
    const float* bc2     = (const float*)d_in[13];
    float* out = (float*)d_out;

    float *p_sa, *p_se, *p_K, *p_Q, *p_V, *p_oth, *p_h1;
    cudaGetSymbolAddress((void**)&p_sa,  g_sa);
    cudaGetSymbolAddress((void**)&p_se,  g_se);
    cudaGetSymbolAddress((void**)&p_K,   g_Kb);
    cudaGetSymbolAddress((void**)&p_Q,   g_Qb);
    cudaGetSymbolAddress((void**)&p_V,   g_Vb);
    cudaGetSymbolAddress((void**)&p_oth, g_oth);
    cudaGetSymbolAddress((void**)&p_h1,  g_h1);

    dim3 grid(BATCH / 128, 1, NAG);
    gemm128_tc<<<grid, 256>>>(states, SDIM, actions, ADIM, We, 0, be, 1, p_sa, SDIM + ADIM);
    gemm128_tc<<<grid, 256>>>(states, SDIM, nullptr, 0,    Wse, 0, bs, 1, p_se, SDIM);
    gemm128_tc<<<grid, 256>>>(p_sa, HID, nullptr, 0, Wk, 1, nullptr, 0, p_K, HID);
    gemm128_tc<<<grid, 256>>>(p_se, HID, nullptr, 0, Wq, 1, nullptr, 0, p_Q, HID);
    gemm128_tc<<<grid, 256>>>(p_sa, HID, nullptr, 0, Wv, 1, bv,      1, p_V, HID);
    attn_kernel<<<BATCH / 4, 128>>>();
    gemm128_tc<<<grid, 256>>>(p_se, HID, p_oth, HID, Wc1, 0, bc1, 1, p_h1, 2 * HID);
    allq_kernel<<<dim3(BATCH / 256, 1, NAG), 256>>>(actions, Wc2, bc2, out);
}